// round 6
// baseline (speedup 1.0000x reference)
#include <cuda_runtime.h>
#include <cuda_fp16.h>
#include <cstdint>
#include <cstddef>

// ---------------- problem constants ----------------
#define B_   8
#define T_   12
#define P_   1000
#define N_   20000
#define E_   60000
#define FP_  32
#define FN_  32
#define H_   12
#define KD_  384                 // GEMM1 K (nodes_x half only)
#define HID_ 768
#define M_   (B_ * N_)           // 160000 rows
#define BP_  (B_ * P_)           // 8000 distinct patch rows

// ---------------- device scratch (static; no allocs allowed) ----------------
__device__ __half g_X[(size_t)M_ * KD_];    // fp16 nodes_x features, [b*N+n][384]
__device__ __half g_W1t[HID_ * KD_];        // W1 top half transposed:  [h][k], k<384
__device__ __half g_W1bt[HID_ * KD_];       // W1 bottom half transposed: [h][k], k = 384+kk
__device__ __half g_Pf[BP_ * KD_];          // patch rows fp16: [b*P+p][t*32+f]
__device__ __half g_PW[(size_t)BP_ * HID_]; // PW = Pf @ W1_bot : [b*P+p][768]
__device__ int    g_off[N_ + 1];
__device__ int    g_edgep[E_];              // patch index p per edge, CSR-sorted by node

// ---------------- fused conversions (no deps) ----------------
#define W1T_WORK (HID_ * HID_)          // 589824
#define NX_WORK  (B_ * T_ * N_ * 4)     // 768000
#define PF_WORK  (B_ * T_ * P_ * 4)     // 384000
__global__ void k_conv(const float* __restrict__ W1, const float* __restrict__ nodes_x,
                       const float* __restrict__ patch) {
    int i = blockIdx.x * blockDim.x + threadIdx.x;
    if (i < W1T_WORK) {
        int k = i / HID_, h = i % HID_;
        __half v = __float2half_rn(W1[i]);
        if (k < KD_) g_W1t[h * KD_ + k] = v;
        else         g_W1bt[h * KD_ + (k - KD_)] = v;
    } else if (i < W1T_WORK + NX_WORK) {
        int j = i - W1T_WORK;
        int q  = j & 3;
        int n  = (j >> 2) % N_;
        int bt = (j >> 2) / N_;
        int b = bt / T_, t = bt % T_;
        const float4* src = (const float4*)(nodes_x + ((size_t)bt * N_ + n) * FN_ + q * 8);
        float4 a = src[0], c = src[1];
        union { __half2 h[4]; uint4 u; } cv;
        cv.h[0] = __floats2half2_rn(a.x, a.y);
        cv.h[1] = __floats2half2_rn(a.z, a.w);
        cv.h[2] = __floats2half2_rn(c.x, c.y);
        cv.h[3] = __floats2half2_rn(c.z, c.w);
        *(uint4*)&g_X[((size_t)(b * N_ + n)) * KD_ + t * FN_ + q * 8] = cv.u;
    } else if (i < W1T_WORK + NX_WORK + PF_WORK) {
        int j = i - W1T_WORK - NX_WORK;
        int q  = j & 3;
        int p  = (j >> 2) % P_;
        int bt = (j >> 2) / P_;
        int b = bt / T_, t = bt % T_;
        const float4* src = (const float4*)(patch + ((size_t)bt * P_ + p) * FP_ + q * 8);
        float4 a = src[0], c = src[1];
        union { __half2 h[4]; uint4 u; } cv;
        cv.h[0] = __floats2half2_rn(a.x, a.y);
        cv.h[1] = __floats2half2_rn(a.z, a.w);
        cv.h[2] = __floats2half2_rn(c.x, c.y);
        cv.h[3] = __floats2half2_rn(c.z, c.w);
        *(uint4*)&g_Pf[((size_t)(b * P_ + p)) * KD_ + t * FP_ + q * 8] = cv.u;
    }
}

// ---------------- single-block CSR build (hist + scan + scatter) ----------------
__global__ void k_csr(const int* __restrict__ mapper, const int* __restrict__ batch) {
    extern __shared__ int scnt[];               // N_ ints = 80000 B
    __shared__ int buf[1024];
    __shared__ int carry;
    int t = threadIdx.x;
    for (int i = t; i < N_; i += 1024) scnt[i] = 0;
    __syncthreads();
    for (int e = t; e < E_; e += 1024) atomicAdd(&scnt[mapper[e]], 1);
    __syncthreads();
    if (t == 0) { carry = 0; g_off[0] = 0; }
    __syncthreads();
    for (int base = 0; base < N_; base += 1024) {
        int i = base + t;
        int v = (i < N_) ? scnt[i] : 0;
        buf[t] = v;
        __syncthreads();
        for (int s = 1; s < 1024; s <<= 1) {
            int add = (t >= s) ? buf[t - s] : 0;
            __syncthreads();
            buf[t] += add;
            __syncthreads();
        }
        int incl = buf[t] + carry;
        if (i < N_) { g_off[i + 1] = incl; scnt[i] = incl - v; }  // scnt := write cursor
        __syncthreads();
        if (t == 1023) carry = incl;
        __syncthreads();
    }
    for (int e = t; e < E_; e += 1024) {
        int n = mapper[e];
        int idx = atomicAdd(&scnt[n], 1);
        g_edgep[idx] = batch[e];
    }
}

// ---------------- mma helpers (legacy HMMA; compute_103-safe) ----------------
__device__ __forceinline__ uint32_t smem_u32(const void* p) {
    uint32_t a;
    asm volatile("{ .reg .u64 t; cvta.to.shared.u64 t, %1; cvt.u32.u64 %0, t; }"
                 : "=r"(a) : "l"(p));
    return a;
}
__device__ __forceinline__ void ldsm4(uint32_t* r, uint32_t addr) {
    asm volatile("ldmatrix.sync.aligned.m8n8.x4.shared.b16 {%0,%1,%2,%3}, [%4];"
                 : "=r"(r[0]), "=r"(r[1]), "=r"(r[2]), "=r"(r[3]) : "r"(addr));
}
__device__ __forceinline__ void mma16816(float* c, const uint32_t* a,
                                         uint32_t b0, uint32_t b1) {
    asm volatile("mma.sync.aligned.m16n8k16.row.col.f32.f16.f16.f32 "
                 "{%0,%1,%2,%3}, {%4,%5,%6,%7}, {%8,%9}, {%0,%1,%2,%3};"
                 : "+f"(c[0]), "+f"(c[1]), "+f"(c[2]), "+f"(c[3])
                 : "r"(a[0]), "r"(a[1]), "r"(a[2]), "r"(a[3]), "r"(b0), "r"(b1));
}
#define CPASYNC16(dst, src) \
    asm volatile("cp.async.cg.shared.global [%0], [%1], 16;" :: "r"(dst), "l"(src))
#define CPCOMMIT() asm volatile("cp.async.commit_group;" ::: "memory")
#define CPWAIT1()  asm volatile("cp.async.wait_group 1;" ::: "memory")
#define CPWAIT0()  asm volatile("cp.async.wait_group 0;" ::: "memory")

#define ROW_PITCH 80

// ---------------- k_pw: PW[8000,768] = Pf @ W1bt^T (tile 64x128, K=384) ----------------
#define PW_STAGE (192 * ROW_PITCH)   // A 64 rows + B 128 rows
__global__ void __launch_bounds__(256, 1)
k_pw()
{
    __shared__ char smem[3 * PW_STAGE];
    const int tid   = threadIdx.x;
    const int lane  = tid & 31;
    const int wid   = tid >> 5;
    const int warpM = wid >> 2;          // 0..1
    const int warpN = wid & 3;           // 0..3
    const int m0    = blockIdx.x * 64;
    const int n0    = blockIdx.y * 128;
    const uint32_t tile_base = smem_u32(smem);

    const int r0 = tid >> 2;             // 0..63
    const int c0 = tid & 3;

    float acc[2][4][4];
#pragma unroll
    for (int mf = 0; mf < 2; ++mf)
#pragma unroll
        for (int nf = 0; nf < 4; ++nf)
#pragma unroll
            for (int q = 0; q < 4; ++q) acc[mf][nf][q] = 0.0f;

#pragma unroll
    for (int s = 0; s < 2; ++s) {
        const int k0 = s * 32;
        uint32_t sA = tile_base + s * PW_STAGE;
        uint32_t sB = sA + 64 * ROW_PITCH;
        CPASYNC16(sA + r0 * ROW_PITCH + c0 * 16,
                  (const void*)&g_Pf[(size_t)(m0 + r0) * KD_ + k0 + c0 * 8]);
        CPASYNC16(sB + r0 * ROW_PITCH + c0 * 16,
                  (const void*)&g_W1bt[(size_t)(n0 + r0) * KD_ + k0 + c0 * 8]);
        CPASYNC16(sB + (r0 + 64) * ROW_PITCH + c0 * 16,
                  (const void*)&g_W1bt[(size_t)(n0 + r0 + 64) * KD_ + k0 + c0 * 8]);
        CPCOMMIT();
    }

#pragma unroll 1
    for (int kt = 0; kt < 12; ++kt) {
        if (kt < 11) { CPWAIT1(); } else { CPWAIT0(); }
        __syncthreads();
        if (kt + 2 < 12) {
            const int k0 = (kt + 2) * 32;
            const int st = (kt + 2) % 3;
            uint32_t sA = tile_base + st * PW_STAGE;
            uint32_t sB = sA + 64 * ROW_PITCH;
            CPASYNC16(sA + r0 * ROW_PITCH + c0 * 16,
                      (const void*)&g_Pf[(size_t)(m0 + r0) * KD_ + k0 + c0 * 8]);
            CPASYNC16(sB + r0 * ROW_PITCH + c0 * 16,
                      (const void*)&g_W1bt[(size_t)(n0 + r0) * KD_ + k0 + c0 * 8]);
            CPASYNC16(sB + (r0 + 64) * ROW_PITCH + c0 * 16,
                      (const void*)&g_W1bt[(size_t)(n0 + r0 + 64) * KD_ + k0 + c0 * 8]);
            CPCOMMIT();
        }
        const int st = kt % 3;
        uint32_t sA = tile_base + st * PW_STAGE;
        uint32_t sB = sA + 64 * ROW_PITCH;
#pragma unroll
        for (int ks = 0; ks < 2; ++ks) {
            uint32_t afr[2][4], bfr[2][4];
#pragma unroll
            for (int mf = 0; mf < 2; ++mf) {
                uint32_t addr = sA + (warpM * 32 + mf * 16 + (lane & 15)) * ROW_PITCH
                                   + (ks * 2 + (lane >> 4)) * 16;
                ldsm4(afr[mf], addr);
            }
#pragma unroll
            for (int nq = 0; nq < 2; ++nq) {
                uint32_t addr = sB + (warpN * 32 + nq * 16 + (lane & 7) + ((lane >> 4) & 1) * 8) * ROW_PITCH
                                   + (ks * 2 + ((lane >> 3) & 1)) * 16;
                ldsm4(bfr[nq], addr);
            }
#pragma unroll
            for (int mf = 0; mf < 2; ++mf)
#pragma unroll
                for (int nq = 0; nq < 2; ++nq) {
                    mma16816(acc[mf][nq * 2],     afr[mf], bfr[nq][0], bfr[nq][1]);
                    mma16816(acc[mf][nq * 2 + 1], afr[mf], bfr[nq][2], bfr[nq][3]);
                }
        }
    }

    // store PW fp16
#pragma unroll
    for (int mf = 0; mf < 2; ++mf)
#pragma unroll
        for (int hr = 0; hr < 2; ++hr) {
            int row = m0 + warpM * 32 + mf * 16 + hr * 8 + (lane >> 2);
#pragma unroll
            for (int nf = 0; nf < 4; ++nf) {
                int col = n0 + warpN * 32 + nf * 8 + (lane & 3) * 2;
                __half2 h = __floats2half2_rn(acc[mf][nf][2 * hr], acc[mf][nf][2 * hr + 1]);
                *(__half2*)&g_PW[(size_t)row * HID_ + col] = h;
            }
        }
}

// ---------------- main GEMM: X(160000x384) @ W1t^T, fused mean/relu/GEMM2 ----------------
// smem: W2 @0 (36864) | b1 @36864 (3072) | tiles @40960 (3*20480) ; reduce reuses tiles
#define SM_W2   0
#define SM_B1   36864
#define SM_TILE 40960
#define STAGE_BYTES 20480
#define SMEM_BYTES  102400

#define NT_   6
#define KT_   12
#define KTG_  (NT_ * KT_)   // 72

__global__ void __launch_bounds__(512, 1)
k_gemm(const float* __restrict__ b1, const float* __restrict__ W2,
       const float* __restrict__ b2, float* __restrict__ out)
{
    extern __shared__ char smem[];
    const int tid   = threadIdx.x;
    const int lane  = tid & 31;
    const int wid   = tid >> 5;
    const int warpM = wid >> 2;          // 0..3
    const int warpN = wid & 3;           // 0..3
    const int m0    = blockIdx.x * 128;

    float* w2s = (float*)(smem + SM_W2);
    float* b1s = (float*)(smem + SM_B1);
    const uint32_t tile_base = smem_u32(smem + SM_TILE);

    for (int i = tid; i < HID_ * H_; i += 512) w2s[i] = W2[i];
    for (int i = tid; i < HID_;      i += 512) b1s[i] = b1[i];
    __syncthreads();

    const int r0 = tid >> 2;
    const int c0 = tid & 3;

    float pers[4][3];
#pragma unroll
    for (int i = 0; i < 4; ++i)
#pragma unroll
        for (int j = 0; j < 3; ++j) pers[i][j] = 0.0f;

    float acc[2][4][4];
#pragma unroll
    for (int mf = 0; mf < 2; ++mf)
#pragma unroll
        for (int nf = 0; nf < 4; ++nf)
#pragma unroll
            for (int q = 0; q < 4; ++q) acc[mf][nf][q] = 0.0f;

#pragma unroll
    for (int s = 0; s < 2; ++s) {
        const int k0 = s * 32;
        uint32_t sA = tile_base + s * STAGE_BYTES;
        uint32_t sB = sA + 128 * ROW_PITCH;
        CPASYNC16(sA + r0 * ROW_PITCH + c0 * 16,
                  (const void*)&g_X[(size_t)(m0 + r0) * KD_ + k0 + c0 * 8]);
        CPASYNC16(sB + r0 * ROW_PITCH + c0 * 16,
                  (const void*)&g_W1t[(size_t)r0 * KD_ + k0 + c0 * 8]);
        CPCOMMIT();
    }

#pragma unroll 1
    for (int ktg = 0; ktg < KTG_; ++ktg) {
        if (ktg < KTG_ - 1) { CPWAIT1(); } else { CPWAIT0(); }
        __syncthreads();

        if (ktg + 2 < KTG_) {
            const int pg  = ktg + 2;
            const int pk0 = (pg % KT_) * 32;
            const int pn0 = (pg / KT_) * 128;
            const int st  = pg % 3;
            uint32_t sA = tile_base + st * STAGE_BYTES;
            uint32_t sB = sA + 128 * ROW_PITCH;
            CPASYNC16(sA + r0 * ROW_PITCH + c0 * 16,
                      (const void*)&g_X[(size_t)(m0 + r0) * KD_ + pk0 + c0 * 8]);
            CPASYNC16(sB + r0 * ROW_PITCH + c0 * 16,
                      (const void*)&g_W1t[(size_t)(pn0 + r0) * KD_ + pk0 + c0 * 8]);
            CPCOMMIT();
        }

        {
            const int st = ktg % 3;
            uint32_t sA = tile_base + st * STAGE_BYTES;
            uint32_t sB = sA + 128 * ROW_PITCH;
#pragma unroll
            for (int ks = 0; ks < 2; ++ks) {
                uint32_t afr[2][4], bfr[2][4];
#pragma unroll
                for (int mf = 0; mf < 2; ++mf) {
                    uint32_t addr = sA + (warpM * 32 + mf * 16 + (lane & 15)) * ROW_PITCH
                                       + (ks * 2 + (lane >> 4)) * 16;
                    ldsm4(afr[mf], addr);
                }
#pragma unroll
                for (int nq = 0; nq < 2; ++nq) {
                    uint32_t addr = sB + (warpN * 32 + nq * 16 + (lane & 7) + ((lane >> 4) & 1) * 8) * ROW_PITCH
                                       + (ks * 2 + ((lane >> 3) & 1)) * 16;
                    ldsm4(bfr[nq], addr);
                }
#pragma unroll
                for (int mf = 0; mf < 2; ++mf)
#pragma unroll
                    for (int nq = 0; nq < 2; ++nq) {
                        mma16816(acc[mf][nq * 2],     afr[mf], bfr[nq][0], bfr[nq][1]);
                        mma16816(acc[mf][nq * 2 + 1], afr[mf], bfr[nq][2], bfr[nq][3]);
                    }
            }
        }

        // ---- n-tile boundary: mean-gather + b1 + relu + fused GEMM2 ----
        if ((ktg % KT_) == (KT_ - 1)) {
            const int n0 = (ktg / KT_) * 128;
#pragma unroll
            for (int mf = 0; mf < 2; ++mf) {
#pragma unroll
                for (int hr = 0; hr < 2; ++hr) {
                    const int rowL = warpM * 32 + mf * 16 + hr * 8 + (lane >> 2);
                    const int m    = m0 + rowL;
                    const int bb   = m / N_;
                    const int nn   = m - bb * N_;
                    const int eb   = g_off[nn];
                    const int ec   = g_off[nn + 1] - eb;
                    const float inv = 1.0f / fmaxf((float)ec, 1.0f);
                    const int colbase = n0 + warpN * 32 + (lane & 3) * 2;

                    float ms[8];
#pragma unroll
                    for (int o = 0; o < 8; ++o) ms[o] = 0.0f;
                    for (int e = 0; e < ec; ++e) {
                        int pp = g_edgep[eb + e];
                        const __half* prow = g_PW + ((size_t)(bb * P_ + pp)) * HID_;
#pragma unroll
                        for (int nf = 0; nf < 4; ++nf) {
                            __half2 hv = *(const __half2*)(prow + colbase + nf * 8);
                            float2 f = __half22float2(hv);
                            ms[nf * 2]     += f.x;
                            ms[nf * 2 + 1] += f.y;
                        }
                    }

                    float p[12];
#pragma unroll
                    for (int o = 0; o < 12; ++o) p[o] = 0.0f;
#pragma unroll
                    for (int nf = 0; nf < 4; ++nf) {
                        int col0 = colbase + nf * 8;
                        float v0 = fmaxf(acc[mf][nf][2 * hr]     + ms[nf * 2]     * inv + b1s[col0],     0.0f);
                        float v1 = fmaxf(acc[mf][nf][2 * hr + 1] + ms[nf * 2 + 1] * inv + b1s[col0 + 1], 0.0f);
                        const float4* wp0 = (const float4*)(w2s + col0 * 12);
                        const float4* wp1 = (const float4*)(w2s + (col0 + 1) * 12);
                        float4 a0 = wp0[0], a1 = wp0[1], a2 = wp0[2];
                        float4 d0 = wp1[0], d1 = wp1[1], d2 = wp1[2];
                        p[0]  += v0 * a0.x + v1 * d0.x;  p[1]  += v0 * a0.y + v1 * d0.y;
                        p[2]  += v0 * a0.z + v1 * d0.z;  p[3]  += v0 * a0.w + v1 * d0.w;
                        p[4]  += v0 * a1.x + v1 * d1.x;  p[5]  += v0 * a1.y + v1 * d1.y;
                        p[6]  += v0 * a1.z + v1 * d1.z;  p[7]  += v0 * a1.w + v1 * d1.w;
                        p[8]  += v0 * a2.x + v1 * d2.x;  p[9]  += v0 * a2.y + v1 * d2.y;
                        p[10] += v0 * a2.z + v1 * d2.z;  p[11] += v0 * a2.w + v1 * d2.w;
                    }
#pragma unroll
                    for (int o = 0; o < 12; ++o) {
                        p[o] += __shfl_xor_sync(0xffffffffu, p[o], 1);
                        p[o] += __shfl_xor_sync(0xffffffffu, p[o], 2);
                    }
                    int q = lane & 3;
                    pers[mf * 2 + hr][0] += p[3 * q + 0];
                    pers[mf * 2 + hr][1] += p[3 * q + 1];
                    pers[mf * 2 + hr][2] += p[3 * q + 2];
                }
            }
#pragma unroll
            for (int mf = 0; mf < 2; ++mf)
#pragma unroll
                for (int nf = 0; nf < 4; ++nf)
#pragma unroll
                    for (int q = 0; q < 4; ++q) acc[mf][nf][q] = 0.0f;
        }
    }

    // ---- cross-warpN reduction through smem (3 buffers), then global write ----
    float* red = (float*)(smem + SM_TILE);  // 3 * 128 * 12 floats
    __syncthreads();
    if (warpN != 0) {
#pragma unroll
        for (int i = 0; i < 4; ++i) {
            int mf = i >> 1, hr = i & 1;
            int rowL = warpM * 32 + mf * 16 + hr * 8 + (lane >> 2);
            int q = lane & 3;
#pragma unroll
            for (int j = 0; j < 3; ++j)
                red[(warpN - 1) * 1536 + rowL * 12 + 3 * q + j] = pers[i][j];
        }
    }
    __syncthreads();
    if (warpN == 0) {
#pragma unroll
        for (int i = 0; i < 4; ++i) {
            int mf = i >> 1, hr = i & 1;
            int rowL = warpM * 32 + mf * 16 + hr * 8 + (lane >> 2);
            int q = lane & 3;
            size_t row = (size_t)(m0 + rowL);
#pragma unroll
            for (int j = 0; j < 3; ++j) {
                int o = 3 * q + j;
                out[row * 12 + o] = pers[i][j]
                                  + red[rowL * 12 + o]
                                  + red[1536 + rowL * 12 + o]
                                  + red[3072 + rowL * 12 + o]
                                  + b2[o];
            }
        }
    }
}

// ---------------- launch ----------------
extern "C" void kernel_launch(void* const* d_in, const int* in_sizes, int n_in,
                              void* d_out, int out_size)
{
    const float* patch  = (const float*)d_in[0];
    const float* nodes  = (const float*)d_in[1];
    const int*   batch  = (const int*)d_in[2];
    const int*   mapper = (const int*)d_in[3];
    const float* W1     = (const float*)d_in[4];
    const float* b1     = (const float*)d_in[5];
    const float* W2     = (const float*)d_in[6];
    const float* b2     = (const float*)d_in[7];
    float*       out    = (float*)d_out;

    // launch order: k_gemm is launch #3 (ncu -s 5 -c 1 captures it)
    k_conv<<<(W1T_WORK + NX_WORK + PF_WORK + 255) / 256, 256>>>(W1, nodes, patch);  // 0
    dim3 pwgrid(BP_ / 64, HID_ / 128);
    k_pw<<<pwgrid, 256>>>();                                                        // 1
    cudaFuncSetAttribute(k_csr, cudaFuncAttributeMaxDynamicSharedMemorySize, N_ * 4);
    k_csr<<<1, 1024, N_ * 4>>>(mapper, batch);                                      // 2
    cudaFuncSetAttribute(k_gemm, cudaFuncAttributeMaxDynamicSharedMemorySize, SMEM_BYTES);
    k_gemm<<<M_ / 128, 512, SMEM_BYTES>>>(b1, W2, b2, out);                         // 3
}